// round 16
// baseline (speedup 1.0000x reference)
#include <cuda_runtime.h>
#include <cuda_bf16.h>
#include <cstdint>

#define NN 2048
#define TJ 32
#define SPLIT 8
#define JCHUNK (NN / SPLIT)      // 256
#define NTILES (JCHUNK / TJ)     // 8
#define LOG2E 1.4426950408889634f
#define ONESB 0x3F803F80u        // bf16x2 {1.0, 1.0}

typedef unsigned long long ull;

// Scratch (device globals; no allocation allowed)
__device__ float    g_h    [2 * NN * 128];          // h[b][n][128] fp32 (residual)
__device__ uint32_t g_vb   [2 * 1024 * 128];        // vperm bf16x2 j-pairs [b][jp][col]
__device__ uint32_t g_mbits[NN * 64];               // adj bit-packed [row][j/32]
__device__ float    g_ei   [2 * NN * 4];            // pre-scaled by log2(e)
__device__ float    g_ej   [2 * NN * 4];            // pre-scaled by log2(e)
__device__ float    g_part [SPLIT * 2 * NN * 128];  // partial AV accumulators
__device__ float    g_psum [SPLIT * 2 * NN * 4];    // partial softmax denominators

__device__ __forceinline__ float ex2(float x) {
    float r;
    asm("ex2.approx.f32 %0, %1;" : "=f"(r) : "f"(x));
    return r;
}
__device__ __forceinline__ uint32_t bf16x2(float hi, float lo) {
    uint32_t r;
    asm("cvt.rn.bf16x2.f32 %0, %1, %2;" : "=r"(r) : "f"(hi), "f"(lo));
    return r;
}

// dynamic smem layout (bytes):
#define VSM_BUF (16 * 136 * 4)            // 8704 per buf (16 jp-rows x 136 u32)
#define MB_OFF  (3 * VSM_BUF)             // 26112; mask bits 128 rows x 12 u32 pitch
#define EJ_OFF  (MB_OFF + 128 * 12 * 4)   // 32256; ej 256 x float4
#define SMEM_SZ (EJ_OFF + 256 * 16)       // 36352

// ---------------------------------------------------------------------------
// Kernel 0: bit-pack adj. Warp reads 32 consecutive ints, ballot -> 1 word.
// ---------------------------------------------------------------------------
__global__ __launch_bounds__(256) void k0_pack(const int* __restrict__ adj) {
    const int wp   = threadIdx.x >> 5;
    const int lane = threadIdx.x & 31;
#pragma unroll
    for (int i = 0; i < 8; ++i) {
        int widx = blockIdx.x * 64 + wp * 8 + i;
        int row  = widx >> 6, w = widx & 63;
        int v = adj[(size_t)row * NN + w * 32 + lane];
        unsigned m = __ballot_sync(0xffffffffu, v != 0);
        if (lane == 0) g_mbits[row * 64 + w] = m;
    }
}

// ---------------------------------------------------------------------------
// Kernel 1: h = x @ w^T, scatter permuted v as bf16x2 j-pairs, ei/ej (log2e).
// 512 blocks x 256 threads; 8 rows/block (thread: col t&127, row-half t>>7).
// vb j-pairs (rows rr, rr+4) exchanged via smem hs tile.
// ---------------------------------------------------------------------------
__global__ __launch_bounds__(256, 3) void k1_proj(const float* __restrict__ x,
                                                  const float* __restrict__ w,
                                                  const float* __restrict__ a) {
    const int t    = threadIdx.x;
    const int r0   = blockIdx.x * 8;
    const int tc   = t & 127;
    const int half = t >> 7;               // rows half*4 .. half*4+3
    const int h    = tc >> 5;
    const int d    = tc & 31;
    const int lane = t & 31;

    __shared__ float ws[128 * 65];
    __shared__ float xs[8 * 64];
    __shared__ float hs[8][128];

#pragma unroll
    for (int k = 0; k < 32; ++k) {
        int idx = t + k * 256;
        ws[(idx >> 6) * 65 + (idx & 63)] = w[idx];
    }
    xs[t]       = x[r0 * 64 + t];
    xs[t + 256] = x[r0 * 64 + t + 256];
    __syncthreads();

    const float a1v = a[h * 64 + d];
    const float a2v = a[h * 64 + 32 + d];
    const float* wrow = &ws[tc * 65];

#pragma unroll
    for (int q = 0; q < 4; ++q) {
        const int rr  = half * 4 + q;
        const int row = r0 + rr;
        float acc = 0.f;
#pragma unroll
        for (int i = 0; i < 64; ++i)
            acc += xs[rr * 64 + i] * wrow[i];
        g_h[row * 128 + tc] = acc;
        hs[rr][tc] = acc;

        float p1 = acc * a1v;
        float p2 = acc * a2v;
#pragma unroll
        for (int off = 16; off; off >>= 1) {
            p1 += __shfl_xor_sync(0xffffffffu, p1, off);
            p2 += __shfl_xor_sync(0xffffffffu, p2, off);
        }
        if (lane == 0) {
            g_ei[row * 4 + h] = p1 * LOG2E;
            g_ej[row * 4 + h] = p2 * LOG2E;
        }
    }
    __syncthreads();

    // vb pack: pairs (rr, rr+4), rr = half*2 + q
    const int b  = r0 >> 11;
    const int n0 = r0 & (NN - 1);
    const int jp = (h * NN + n0) >> 3;
#pragma unroll
    for (int q = 0; q < 2; ++q) {
        const int rr = half * 2 + q;
        g_vb[(size_t)(b * 1024 + jp) * 128 + rr * 32 + d]
            = bf16x2(hs[rr + 4][tc], hs[rr][tc]);
    }
}

// ---------------------------------------------------------------------------
// Kernel 2: attention via bf16 mma.sync.m16n8k16, 3-deep cp.async pipeline.
// psum computed by an extra ones-column MMA per (ks,h) reusing the A-frags
// (tensor pipe does the rowsums; no fma tree, no end shuffles).
// ---------------------------------------------------------------------------
__global__ __launch_bounds__(256, 2) void k2_attn() {
    extern __shared__ __align__(16) char smem[];
    const int t  = threadIdx.x;
    const int wp = t >> 5;
    const int qr = (t & 31) >> 2;
    const int qc = t & 3;
    const int sp = blockIdx.x & 7;
    const int nt = (blockIdx.x >> 3) & 15;
    const int b  = blockIdx.x >> 7;
    const int n0 = nt * 128;
    const int js = sp * JCHUNK;
    const int r0 = wp * 16;

    const float4 eiA = *(const float4*)&g_ei[(size_t)(b * NN + n0 + r0 + qr) * 4];
    const float4 eiB = *(const float4*)&g_ei[(size_t)(b * NN + n0 + r0 + 8 + qr) * 4];

    float acc[16][4];
#pragma unroll
    for (int i = 0; i < 16; ++i)
#pragma unroll
        for (int j = 0; j < 4; ++j) acc[i][j] = 0.f;
    float accp[4][4];                      // psum accumulators [h][c]
#pragma unroll
    for (int i = 0; i < 4; ++i)
#pragma unroll
        for (int j = 0; j < 4; ++j) accp[i][j] = 0.f;

    uint32_t sbase;
    asm("{ .reg .u64 u; cvta.to.shared.u64 u, %1; cvt.u32.u64 %0, u; }" : "=r"(sbase) : "l"(smem));

    auto issueV = [&](int tile) {
        const int jp0 = (js + tile * TJ) >> 1;
        const uint32_t vbase = sbase + (tile % 3) * VSM_BUF;
#pragma unroll
        for (int k = 0; k < 2; ++k) {
            int c = t + k * 256;
            int row = c >> 5, o = c & 31;
            uint32_t dst = vbase + row * 544 + o * 16;
            const uint32_t* src = g_vb + (size_t)(b * 1024 + jp0 + row) * 128 + o * 4;
            asm volatile("cp.async.cg.shared.global [%0], [%1], 16;" :: "r"(dst), "l"(src));
        }
        asm volatile("cp.async.commit_group;");
    };

    // upfront: mask bits (128 rows x 8 words, pitch 12) + ej chunk (256 x f4)
    {
        const int row = t >> 1, half = t & 1;
        uint32_t dst = sbase + MB_OFF + row * 48 + half * 16;
        const uint32_t* src = g_mbits + (size_t)(n0 + row) * 64 + (js >> 5) + half * 4;
        asm volatile("cp.async.cg.shared.global [%0], [%1], 16;" :: "r"(dst), "l"(src));
        uint32_t dst2 = sbase + EJ_OFF + t * 16;
        const float* src2 = g_ej + (size_t)(b * NN + js + t) * 4;
        asm volatile("cp.async.cg.shared.global [%0], [%1], 16;" :: "r"(dst2), "l"(src2));
    }
    issueV(0);
    issueV(1);
    issueV(2);

    const uint32_t* mb  = (const uint32_t*)(smem + MB_OFF);
    const float4*  ejs4 = (const float4*)(smem + EJ_OFF);

    for (int tile = 0; tile < NTILES; ++tile) {
        asm volatile("cp.async.wait_group 2;" ::: "memory");
        __syncthreads();
        const uint32_t* vb = (const uint32_t*)(smem + (tile % 3) * VSM_BUF);

        const uint32_t wA = mb[(r0 + qr) * 12 + tile];
        const uint32_t wB = mb[(r0 + 8 + qr) * 12 + tile];

#pragma unroll
        for (int ks = 0; ks < 2; ++ks) {
            const int jb = ks * 16;
            const int b0 = jb + 2 * qc;
            const float pmA0 = (float)((wA >> b0) & 1u);
            const float pmA1 = (float)((wA >> (b0 + 1)) & 1u);
            const float pmA2 = (float)((wA >> (b0 + 8)) & 1u);
            const float pmA3 = (float)((wA >> (b0 + 9)) & 1u);
            const float pmB0 = (float)((wB >> b0) & 1u);
            const float pmB1 = (float)((wB >> (b0 + 1)) & 1u);
            const float pmB2 = (float)((wB >> (b0 + 8)) & 1u);
            const float pmB3 = (float)((wB >> (b0 + 9)) & 1u);
            const float4 ej0 = ejs4[tile * 32 + jb + 2 * qc];
            const float4 ej1 = ejs4[tile * 32 + jb + 2 * qc + 1];
            const float4 ej2 = ejs4[tile * 32 + jb + 2 * qc + 8];
            const float4 ej3 = ejs4[tile * 32 + jb + 2 * qc + 9];
#pragma unroll
            for (int h = 0; h < 4; ++h) {
                const float ei0 = (&eiA.x)[h], ei1 = (&eiB.x)[h];
                const float ejv0 = (&ej0.x)[h], ejv1 = (&ej1.x)[h];
                const float ejv2 = (&ej2.x)[h], ejv3 = (&ej3.x)[h];
                float e;
                float pA0, pA1, pA2, pA3, pB0, pB1, pB2, pB3;
                e = ei0 + ejv0; e = fmaxf(e, 0.2f * e); pA0 = ex2(e) * pmA0;
                e = ei0 + ejv1; e = fmaxf(e, 0.2f * e); pA1 = ex2(e) * pmA1;
                e = ei0 + ejv2; e = fmaxf(e, 0.2f * e); pA2 = ex2(e) * pmA2;
                e = ei0 + ejv3; e = fmaxf(e, 0.2f * e); pA3 = ex2(e) * pmA3;
                e = ei1 + ejv0; e = fmaxf(e, 0.2f * e); pB0 = ex2(e) * pmB0;
                e = ei1 + ejv1; e = fmaxf(e, 0.2f * e); pB1 = ex2(e) * pmB1;
                e = ei1 + ejv2; e = fmaxf(e, 0.2f * e); pB2 = ex2(e) * pmB2;
                e = ei1 + ejv3; e = fmaxf(e, 0.2f * e); pB3 = ex2(e) * pmB3;
                const uint32_t a0 = bf16x2(pA1, pA0);
                const uint32_t a1 = bf16x2(pB1, pB0);
                const uint32_t a2 = bf16x2(pA3, pA2);
                const uint32_t a3 = bf16x2(pB3, pB2);
#pragma unroll
                for (int n = 0; n < 4; ++n) {
                    const int col = h * 32 + n * 8 + qr;
                    const uint32_t v0 = vb[(ks * 8 + qc) * 136 + col];
                    const uint32_t v1 = vb[(ks * 8 + qc + 4) * 136 + col];
                    float* c = acc[h * 4 + n];
                    asm("mma.sync.aligned.m16n8k16.row.col.f32.bf16.bf16.f32 "
                        "{%0,%1,%2,%3}, {%4,%5,%6,%7}, {%8,%9}, {%0,%1,%2,%3};"
                        : "+f"(c[0]), "+f"(c[1]), "+f"(c[2]), "+f"(c[3])
                        : "r"(a0), "r"(a1), "r"(a2), "r"(a3), "r"(v0), "r"(v1));
                }
                // psum: same A-frags vs ones-column B (tensor-pipe rowsum)
                {
                    float* c = accp[h];
                    asm("mma.sync.aligned.m16n8k16.row.col.f32.bf16.bf16.f32 "
                        "{%0,%1,%2,%3}, {%4,%5,%6,%7}, {%8,%9}, {%0,%1,%2,%3};"
                        : "+f"(c[0]), "+f"(c[1]), "+f"(c[2]), "+f"(c[3])
                        : "r"(a0), "r"(a1), "r"(a2), "r"(a3), "r"(ONESB), "r"(ONESB));
                }
            }
        }
        __syncthreads();
        if (tile + 3 < NTILES) issueV(tile + 3);
    }

    // psum writeback: acc_p[h][0] = rowsum(r0+qr), acc_p[h][2] = rowsum(r0+8+qr)
    if (qc == 0) {
        size_t base = ((size_t)(sp * 2 + b) * NN + n0 + r0);
        *(float4*)&g_psum[(base + qr) * 4]
            = make_float4(accp[0][0], accp[1][0], accp[2][0], accp[3][0]);
        *(float4*)&g_psum[(base + 8 + qr) * 4]
            = make_float4(accp[0][2], accp[1][2], accp[2][2], accp[3][2]);
    }

    // accumulator writeback
    {
        size_t base0 = ((size_t)(sp * 2 + b) * NN + n0 + r0 + qr) * 128;
        size_t base1 = base0 + 8 * 128;
#pragma unroll
        for (int h = 0; h < 4; ++h)
#pragma unroll
            for (int n = 0; n < 4; ++n) {
                const int col = h * 32 + n * 8 + qc * 2;
                const float* c = acc[h * 4 + n];
                *(float2*)&g_part[base0 + col] = make_float2(c[0], c[1]);
                *(float2*)&g_part[base1 + col] = make_float2(c[2], c[3]);
            }
    }
}

// ---------------------------------------------------------------------------
// Kernel 3: reduce split partials, normalize, residual, LayerNorm.
// ---------------------------------------------------------------------------
__global__ __launch_bounds__(128) void k3_epi(const float* __restrict__ gamma,
                                              const float* __restrict__ beta,
                                              float*       __restrict__ out) {
    const int t  = threadIdx.x;
    const int b  = blockIdx.x >> 10;
    const int n0 = (blockIdx.x & 1023) * 2;
    const int h  = t >> 5;
    const int d  = t & 31;

    __shared__ float red1[4][2], red2[4][2];

    const float gma = gamma[t];
    const float bta = beta[t];
    float ys[2];

#pragma unroll
    for (int r = 0; r < 2; ++r) {
        const int n = n0 + r;
        float accv = 0.f, rsum = 0.f;
#pragma unroll
        for (int spp = 0; spp < SPLIT; ++spp) {
            accv += g_part[(size_t)((spp * 2 + b) * NN + n) * 128 + t];
            rsum += g_psum[((size_t)(spp * 2 + b) * NN + n) * 4 + h];
        }
        float y = accv / rsum + g_h[(size_t)(b * NN + n) * 128 + t];
        ys[r] = y;
        float s1 = y, s2 = y * y;
#pragma unroll
        for (int off = 16; off; off >>= 1) {
            s1 += __shfl_xor_sync(0xffffffffu, s1, off);
            s2 += __shfl_xor_sync(0xffffffffu, s2, off);
        }
        if (d == 0) { red1[h][r] = s1; red2[h][r] = s2; }
    }
    __syncthreads();
#pragma unroll
    for (int r = 0; r < 2; ++r) {
        float s1 = red1[0][r] + red1[1][r] + red1[2][r] + red1[3][r];
        float s2 = red2[0][r] + red2[1][r] + red2[2][r] + red2[3][r];
        float mu  = s1 * (1.f / 128.f);
        float var = s2 * (1.f / 128.f) - mu * mu;
        float inv = rsqrtf(var + 1e-5f);
        out[(size_t)(b * NN + n0 + r) * 128 + t] = (ys[r] - mu) * inv * gma + bta;
    }
}

extern "C" void kernel_launch(void* const* d_in, const int* in_sizes, int n_in,
                              void* d_out, int out_size) {
    const float* x     = (const float*)d_in[0];
    const int*   adj   = (const int*)  d_in[1];
    const float* w     = (const float*)d_in[2];
    const float* a     = (const float*)d_in[3];
    const float* gamma = (const float*)d_in[4];
    const float* beta  = (const float*)d_in[5];

    static int smem_set = 0;
    if (!smem_set) {
        cudaFuncSetAttribute(k2_attn, cudaFuncAttributeMaxDynamicSharedMemorySize, SMEM_SZ);
        smem_set = 1;
    }

    k0_pack<<<2048, 256>>>(adj);
    k1_proj<<<512, 256>>>(x, w, a);
    k2_attn<<<16 * SPLIT * 2, 256, SMEM_SZ>>>();
    k3_epi<<<2048, 128>>>(gamma, beta, (float*)d_out);
}